// round 12
// baseline (speedup 1.0000x reference)
#include <cuda_runtime.h>
#include <cstdint>

// VQ nearest-codebook, fp32-exact. fma.rn.f32x2 lanes carry a (d, d+1) PAIR:
// both operands load as natural 8B pairs (no dup movs), one step covers 2 d.
// Lane tile: 4 points (distributed) x 8 codewords (warp-broadcast).
// Block = 128 points (2 (b,h) rows), 256 threads, 16 chunks of 64 codewords.
// (Resubmission after broker-side container failure; source identical.)

#define DD 64
#define ND2 32            // d-pairs
#define KTOT 1024
#define TKC 64            // codewords per chunk
#define NCHUNK (KTOT / TKC)
#define PTS 128
#define NTHREADS 256

// smem (floats): psA[32][128], psB[32][128], cs0[32][128], cs1[32][128]
#define PSA_OFF 0
#define PSB_OFF 4096
#define CS0_OFF 8192
#define CS1_OFF 12288
#define SMEM_FLOATS 16384   // 64 KB

__device__ float g_cbT2[ND2 * KTOT * 2];  // [d2][k][2] = (cb[k][2d2], cb[k][2d2+1])
__device__ float g_cnorm[KTOT];

#define FMA2(d, a, b) \
    asm("fma.rn.f32x2 %0, %1, %2, %0;" : "+l"(d) : "l"(a), "l"(b))
#define UNPACK2(u0, u1, v) \
    asm("mov.b64 {%0, %1}, %2;" : "=r"(u0), "=r"(u1) : "l"(v))
#define CP_ASYNC16(dst, src) \
    asm volatile("cp.async.ca.shared.global [%0], [%1], 16;" :: "r"(dst), "l"(src))
#define CP_COMMIT() asm volatile("cp.async.commit_group;" ::: "memory")
#define CP_WAIT(n)  asm volatile("cp.async.wait_group %0;" :: "n"(n) : "memory")

__device__ __forceinline__ uint32_t ord_f32(float f) {
    uint32_t u = __float_as_uint(f);
    return (u & 0x80000000u) ? ~u : (u | 0x80000000u);
}

// ---------------- prep: d-pair-interleaved codebook + norms -----------------
__global__ void __launch_bounds__(NTHREADS)
prep_cb(const float* __restrict__ cb) {
    int k = blockIdx.x * blockDim.x + threadIdx.x;
    if (k >= KTOT) return;
    float s = 0.f;
#pragma unroll
    for (int d2 = 0; d2 < ND2; d2++) {
        float2 v = *(const float2*)(cb + (size_t)k * DD + 2 * d2);
        s += v.x * v.x + v.y * v.y;
        *(float2*)(g_cbT2 + (size_t)d2 * (KTOT * 2) + 2 * k) = v;
    }
    g_cnorm[k] = s;
}

// ---------------- main fused kernel -----------------------------------------
__global__ void __launch_bounds__(NTHREADS, 1)
vq_kernel(const float* __restrict__ x, const float* __restrict__ cb,
          float* __restrict__ out, int write_idx) {
    extern __shared__ float smem[];
    float* psA = smem + PSA_OFF;   // [32][128]: (d,d+1) pairs of pts 4g, 4g+1
    float* psB = smem + PSB_OFF;   // [32][128]: pairs of pts 4g+2, 4g+3
    float* const cs_ptr[2] = {smem + CS0_OFF, smem + CS1_OFF};

    const int tid = threadIdx.x;
    const int wid = tid >> 5;      // warp -> codewords 8*wid..8*wid+7 of chunk
    const int tx  = tid & 31;      // lane -> points 4*tx..4*tx+3

    const int bh0 = blockIdx.x * 2;
    const int b  = bh0 >> 6;
    const int h0 = bh0 & 63;
    const float* xbase = x + (size_t)b * (DD * 4096) + (size_t)h0 * 64;

    uint32_t sbase;
    asm("{ .reg .u64 t; cvta.to.shared.u64 t, %1; cvt.u32.u64 %0, t; }"
        : "=r"(sbase) : "l"(smem));
    const uint32_t cs_u32[2] = {sbase + CS0_OFF * 4u, sbase + CS1_OFF * 4u};

    // cp.async slots: thread covers 64B of one d2-row per chunk.
    const int cp_d2  = tid >> 3;           // 0..31
    const int cp_seg = (tid & 7) * 16;     // float offset within row (0..112)

    // ---- Point tile fill: x[b][d][h][w] -> d-pair interleaved psA/psB ----
    for (int i = tid; i < DD * 32; i += NTHREADS) {
        int d  = i >> 5;
        int p4 = (i & 31) * 4;
        float4 v = *(const float4*)(xbase + (size_t)d * 4096 + (p4 >> 6) * 64 + (p4 & 63));
        int d2 = d >> 1, par = d & 1;
        float e[4] = {v.x, v.y, v.z, v.w};
#pragma unroll
        for (int q = 0; q < 4; q++) {
            int p = p4 + q, g = p >> 2, s = p & 3;
            float* dst = (s < 2) ? psA : psB;
            dst[d2 * 128 + g * 4 + (s & 1) * 2 + par] = e[q];
        }
    }

    // Prefetch chunk 0.
#pragma unroll
    for (int q = 0; q < 4; q++)
        CP_ASYNC16(cs_u32[0] + (uint32_t)(cp_d2 * 128 + cp_seg + q * 4) * 4u,
                   g_cbT2 + (size_t)cp_d2 * (KTOT * 2) + cp_seg + q * 4);
    CP_COMMIT();

    // Per-lane best for its 4 points: (ord(d2) << 32) | codeword.
    unsigned long long best[4];
#pragma unroll
    for (int p = 0; p < 4; p++) best[p] = 0xFFFFFFFFFFFFFFFFull;

    for (int j = 0; j < NCHUNK; j++) {
        const int buf = j & 1;
        if (j + 1 < NCHUNK) {
            const int cwoff1 = (j + 1) * TKC * 2;
#pragma unroll
            for (int q = 0; q < 4; q++)
                CP_ASYNC16(cs_u32[buf ^ 1] + (uint32_t)(cp_d2 * 128 + cp_seg + q * 4) * 4u,
                           g_cbT2 + (size_t)cp_d2 * (KTOT * 2) + cwoff1 + cp_seg + q * 4);
            CP_COMMIT();
            CP_WAIT(1);
        } else {
            CP_WAIT(0);
        }
        __syncthreads();

        const float* csb = cs_ptr[buf] + wid * 16;   // warp's 8 cw (d-pairs)
        const float* pa  = psA + tx * 4;
        const float* pb  = psB + tx * 4;

        unsigned long long acc[4][8];
#pragma unroll
        for (int p = 0; p < 4; p++)
#pragma unroll
            for (int c = 0; c < 8; c++) acc[p][c] = 0ull;

#pragma unroll 2
        for (int d2 = 0; d2 < ND2; d2++) {
            // a: 2 dense distributed LDS.128 (pts 4tx..4tx+3 as d-pairs)
            ulonglong2 A = *(const ulonglong2*)(pa + d2 * 128);
            ulonglong2 B = *(const ulonglong2*)(pb + d2 * 128);
            // b: 4 broadcast LDS.128 (warp's 8 codewords as d-pairs)
            const ulonglong2* cw = (const ulonglong2*)(csb + d2 * 128);
            ulonglong2 c01 = cw[0], c23 = cw[1], c45 = cw[2], c67 = cw[3];
            FMA2(acc[0][0], A.x, c01.x); FMA2(acc[0][1], A.x, c01.y);
            FMA2(acc[0][2], A.x, c23.x); FMA2(acc[0][3], A.x, c23.y);
            FMA2(acc[0][4], A.x, c45.x); FMA2(acc[0][5], A.x, c45.y);
            FMA2(acc[0][6], A.x, c67.x); FMA2(acc[0][7], A.x, c67.y);
            FMA2(acc[1][0], A.y, c01.x); FMA2(acc[1][1], A.y, c01.y);
            FMA2(acc[1][2], A.y, c23.x); FMA2(acc[1][3], A.y, c23.y);
            FMA2(acc[1][4], A.y, c45.x); FMA2(acc[1][5], A.y, c45.y);
            FMA2(acc[1][6], A.y, c67.x); FMA2(acc[1][7], A.y, c67.y);
            FMA2(acc[2][0], B.x, c01.x); FMA2(acc[2][1], B.x, c01.y);
            FMA2(acc[2][2], B.x, c23.x); FMA2(acc[2][3], B.x, c23.y);
            FMA2(acc[2][4], B.x, c45.x); FMA2(acc[2][5], B.x, c45.y);
            FMA2(acc[2][6], B.x, c67.x); FMA2(acc[2][7], B.x, c67.y);
            FMA2(acc[3][0], B.y, c01.x); FMA2(acc[3][1], B.y, c01.y);
            FMA2(acc[3][2], B.y, c23.x); FMA2(acc[3][3], B.y, c23.y);
            FMA2(acc[3][4], B.y, c45.x); FMA2(acc[3][5], B.y, c45.y);
            FMA2(acc[3][6], B.y, c67.x); FMA2(acc[3][7], B.y, c67.y);
        }

        // dot = even-d partial + odd-d partial; d2 = ||c||^2 - 2 dot.
        // Packed u64 min = first-occurrence tie-break (idx in low bits).
        const int cw0 = j * TKC + wid * 8;
        float4 n0 = __ldg((const float4*)(g_cnorm + cw0));
        float4 n1 = __ldg((const float4*)(g_cnorm + cw0 + 4));
        const float nn[8] = {n0.x, n0.y, n0.z, n0.w, n1.x, n1.y, n1.z, n1.w};
#pragma unroll
        for (int c = 0; c < 8; c++) {
#pragma unroll
            for (int p = 0; p < 4; p++) {
                uint32_t lo, hi;
                UNPACK2(lo, hi, acc[p][c]);
                float dot = __uint_as_float(lo) + __uint_as_float(hi);
                float d2v = fmaf(-2.f, dot, nn[c]);
                unsigned long long key =
                    ((unsigned long long)ord_f32(d2v) << 32) | (unsigned)(cw0 + c);
                if (key < best[p]) best[p] = key;
            }
        }
        __syncthreads();   // all warps done with cs[buf] before refill
    }

    // Cross-warp merge (each warp covered a disjoint codeword subset).
    unsigned long long* mb = (unsigned long long*)smem;   // [128][8] u64 = 8 KB
#pragma unroll
    for (int p = 0; p < 4; p++) mb[(4 * tx + p) * 8 + wid] = best[p];
    __syncthreads();

    int* bidx = (int*)(smem + 2048);   // 128 ints
    if (tid < PTS) {
        unsigned long long m = mb[tid * 8];
#pragma unroll
        for (int w = 1; w < 8; w++) {
            unsigned long long v = mb[tid * 8 + w];
            if (v < m) m = v;
        }
        bidx[tid] = (int)(m & 0xFFFFFFFFull);
    }
    __syncthreads();

    // Gather winning rows coalesced, then transposed store.
    float* tmp = smem + 2304;   // [128][68] floats
    for (int i = tid; i < PTS * 16; i += NTHREADS) {
        int p  = i >> 4;
        int d4 = (i & 15) * 4;
        *(float4*)(tmp + p * 68 + d4) =
            *(const float4*)(cb + (size_t)bidx[p] * DD + d4);
    }
    __syncthreads();
    float* qbase = out + (size_t)b * (DD * 4096) + (size_t)h0 * 64;
    for (int i = tid; i < DD * 32; i += NTHREADS) {
        int d  = i >> 5;
        int p4 = (i & 31) * 4;
        float4 v;
        v.x = tmp[(p4 + 0) * 68 + d];
        v.y = tmp[(p4 + 1) * 68 + d];
        v.z = tmp[(p4 + 2) * 68 + d];
        v.w = tmp[(p4 + 3) * 68 + d];
        *(float4*)(qbase + (size_t)d * 4096 + (p4 >> 6) * 64 + (p4 & 63)) = v;
    }

    if (write_idx && tid < PTS) {
        out[(size_t)4194304 + (size_t)bh0 * 64 + tid] = (float)bidx[tid];
    }
}

// ---------------- launch -----------------------------------------------------
extern "C" void kernel_launch(void* const* d_in, const int* in_sizes, int n_in,
                              void* d_out, int out_size) {
    const float* x  = (const float*)d_in[0];
    const float* cb = (const float*)d_in[1];
    if (n_in >= 2 && in_sizes[0] == KTOT * DD && in_sizes[1] == 16 * 64 * 64 * 64) {
        x  = (const float*)d_in[1];
        cb = (const float*)d_in[0];
    }
    float* out = (float*)d_out;

    const int smem_bytes = SMEM_FLOATS * (int)sizeof(float);
    cudaFuncSetAttribute(vq_kernel, cudaFuncAttributeMaxDynamicSharedMemorySize,
                         smem_bytes);

    int write_idx = (out_size >= 4194304 + 65536) ? 1 : 0;
    prep_cb<<<(KTOT + NTHREADS - 1) / NTHREADS, NTHREADS>>>(cb);
    vq_kernel<<<512, NTHREADS, smem_bytes>>>(x, cb, out, write_idx);
}

// round 13
// speedup vs baseline: 1.3989x; 1.3989x over previous
#include <cuda_runtime.h>
#include <cstdint>

// VQ nearest-codebook via classic tensor-core mma.sync (m16n8k8, tf32),
// 3-term Dekker split for fp32-grade accuracy: S = Xhi*Chi + Xlo*Chi + Xhi*Clo.
// Operands pre-permuted into fragment order (1 LDS.128 per fragment).
// CTA = 128 points (2 (b,h) rows), 8 warps; warp = 16 points x all cw.

#define DD 64
#define KTOT 1024
#define PTS 128
#define NTHREADS 256
#define NCHUNK 16            // chunks of 64 codewords
#define CHUNK_F 5120         // floats per permuted B chunk (8 nt * 640)
#define NT_STRIDE 640        // 32 lanes * 20
#define L_STRIDE 20          // padded lane stride (bank-conflict-free)

// smem float offsets
#define A_HI_OFF 0           // 8 warps * 1024
#define A_LO_OFF 8192
#define B0_OFF   16384       // 5120
#define B1_OFF   21504
#define SMEM_FLOATS 26624    // 104 KB

__device__ float g_Bhi[NCHUNK * CHUNK_F];
__device__ float g_Blo[NCHUNK * CHUNK_F];
__device__ float g_cnorm[KTOT];

#define CP_ASYNC16(dst, src) \
    asm volatile("cp.async.ca.shared.global [%0], [%1], 16;" :: "r"(dst), "l"(src))
#define CP_COMMIT() asm volatile("cp.async.commit_group;" ::: "memory")
#define CP_WAIT0()  asm volatile("cp.async.wait_group 0;" ::: "memory")

#define MMA_TF32(d, a0, a1, a2, a3, b0, b1)                                    \
    asm volatile("mma.sync.aligned.m16n8k8.row.col.f32.tf32.tf32.f32 "         \
        "{%0,%1,%2,%3}, {%4,%5,%6,%7}, {%8,%9}, {%0,%1,%2,%3};"                \
        : "+f"((d)[0]), "+f"((d)[1]), "+f"((d)[2]), "+f"((d)[3])               \
        : "r"(a0), "r"(a1), "r"(a2), "r"(a3), "r"(b0), "r"(b1))

__device__ __forceinline__ float tf32r(float v) {
    uint32_t r;
    asm("cvt.rna.tf32.f32 %0, %1;" : "=r"(r) : "f"(v));
    return __uint_as_float(r);
}
__device__ __forceinline__ uint32_t ord_f32(float f) {
    uint32_t u = __float_as_uint(f);
    return (u & 0x80000000u) ? ~u : (u | 0x80000000u);
}

// ---- prep: split codebook into tf32 hi/lo, permuted into fragment order ----
// B frag (k8 x n8, col-major): b0 = (row tig, col g), b1 = (row tig+4, col g).
// addr = chunk*5120 + nt*640 + (g*4+tig)*20 + kk*2 + reg
__global__ void __launch_bounds__(NTHREADS)
prep_cb(const float* __restrict__ cb) {
    int k = blockIdx.x * blockDim.x + threadIdx.x;
    if (k >= KTOT) return;
    const int chunk = k >> 6, ck = k & 63, nt = ck >> 3, g = ck & 7;
    float s = 0.f;
#pragma unroll
    for (int d = 0; d < DD; d++) {
        float v = cb[(size_t)k * DD + d];
        s += v * v;
        float hi = tf32r(v);
        float lo = tf32r(v - hi);
        int kk = d >> 3, c = d & 7, tig = c & 3, reg = c >> 2;
        int addr = chunk * CHUNK_F + nt * NT_STRIDE + (g * 4 + tig) * L_STRIDE
                 + kk * 2 + reg;
        g_Bhi[addr] = hi;
        g_Blo[addr] = lo;
    }
    g_cnorm[k] = s;
}

// ---- main: GEMM + fused argmin + gather -----------------------------------
__global__ void __launch_bounds__(NTHREADS, 2)
vq_main(const float* __restrict__ x, const float* __restrict__ cb,
        float* __restrict__ out, int write_idx) {
    extern __shared__ float smem[];
    const int tid  = threadIdx.x;
    const int w    = tid >> 5;
    const int lane = tid & 31;
    const int g    = lane >> 2;     // groupID
    const int tig  = lane & 3;      // thread-in-group

    const int bh0 = blockIdx.x * 2;
    const int b   = bh0 >> 6;
    const int h0  = bh0 & 63;
    const float* xbase = x + (size_t)b * (DD * 4096) + (size_t)h0 * 64;

    uint32_t sbase;
    asm("{ .reg .u64 t; cvta.to.shared.u64 t, %1; cvt.u32.u64 %0, t; }"
        : "=r"(sbase) : "l"(smem));

    // Prefetch phase 0 (chunk 0 hi) into B0. 20 floats/thread, linear.
#pragma unroll
    for (int q = 0; q < 5; q++)
        CP_ASYNC16(sbase + (uint32_t)(B0_OFF + tid * L_STRIDE + q * 4) * 4u,
                   g_Bhi + tid * L_STRIDE + q * 4);
    CP_COMMIT();

    // Stage A: x -> tf32 hi/lo in fragment order.
    // A frag (m16 x k8, row): a0=(g,tig) a1=(g+8,tig) a2=(g,tig+4) a3=(g+8,tig+4)
    // addr = warp*1024 + kk*128 + (g*4+tig)*4 + reg, reg = (c>=4)*2 + (r>=8)
    for (int i = tid; i < DD * 32; i += NTHREADS) {
        int d  = i >> 5;
        int p4 = (i & 31) * 4;
        float4 v = *(const float4*)(xbase + (size_t)d * 4096 + (p4 >> 6) * 64 + (p4 & 63));
        float e[4] = {v.x, v.y, v.z, v.w};
        int kk = d >> 3, c = d & 7, tg = c & 3, chalf = (c >> 2) * 2;
#pragma unroll
        for (int q = 0; q < 4; q++) {
            int p = p4 + q, w2 = p >> 4, r = p & 15, gg = r & 7, half = r >> 3;
            int idx = w2 * 1024 + kk * 128 + (gg * 4 + tg) * 4 + chalf + half;
            float hi = tf32r(e[q]);
            smem[A_HI_OFF + idx] = hi;
            smem[A_LO_OFF + idx] = tf32r(e[q] - hi);
        }
    }

    const float* Ahi = smem + A_HI_OFF + w * 1024;
    const float* Alo = smem + A_LO_OFF + w * 1024;

    unsigned long long best0 = 0xFFFFFFFFFFFFFFFFull;  // row w*16+g
    unsigned long long best1 = 0xFFFFFFFFFFFFFFFFull;  // row w*16+g+8
    float acc[8][4];

    // 32 phases: chunk = p>>1; even p = hi (XhiBhi + XloBhi), odd p = lo (XhiBlo)
    for (int p = 0; p < 32; p++) {
        CP_WAIT0();
        __syncthreads();   // buf(p) visible to all; buf(p^1) readers done

        // Prefetch phase p+1 into the other buffer (overlaps compute).
        if (p + 1 < 32) {
            const int pc = (p + 1) >> 1;
            const float* src = (((p + 1) & 1) ? g_Blo : g_Bhi) + pc * CHUNK_F;
            const uint32_t dstb =
                sbase + (uint32_t)((((p + 1) & 1) ? B1_OFF : B0_OFF)) * 4u;
#pragma unroll
            for (int q = 0; q < 5; q++)
                CP_ASYNC16(dstb + (uint32_t)(tid * L_STRIDE + q * 4) * 4u,
                           src + tid * L_STRIDE + q * 4);
            CP_COMMIT();
        }

        const float* B = smem + ((p & 1) ? B1_OFF : B0_OFF);

        if (!(p & 1)) {
#pragma unroll
            for (int nt = 0; nt < 8; nt++)
#pragma unroll
                for (int c = 0; c < 4; c++) acc[nt][c] = 0.f;
#pragma unroll
            for (int kk2 = 0; kk2 < 4; kk2++) {
                uint4 ah0 = *(const uint4*)(Ahi + (2 * kk2 + 0) * 128 + lane * 4);
                uint4 ah1 = *(const uint4*)(Ahi + (2 * kk2 + 1) * 128 + lane * 4);
                uint4 al0 = *(const uint4*)(Alo + (2 * kk2 + 0) * 128 + lane * 4);
                uint4 al1 = *(const uint4*)(Alo + (2 * kk2 + 1) * 128 + lane * 4);
#pragma unroll
                for (int nt = 0; nt < 8; nt++) {
                    uint4 bb = *(const uint4*)(B + nt * NT_STRIDE + lane * L_STRIDE + kk2 * 4);
                    MMA_TF32(acc[nt], ah0.x, ah0.y, ah0.z, ah0.w, bb.x, bb.y);
                    MMA_TF32(acc[nt], ah1.x, ah1.y, ah1.z, ah1.w, bb.z, bb.w);
                    MMA_TF32(acc[nt], al0.x, al0.y, al0.z, al0.w, bb.x, bb.y);
                    MMA_TF32(acc[nt], al1.x, al1.y, al1.z, al1.w, bb.z, bb.w);
                }
            }
        } else {
#pragma unroll
            for (int kk2 = 0; kk2 < 4; kk2++) {
                uint4 ah0 = *(const uint4*)(Ahi + (2 * kk2 + 0) * 128 + lane * 4);
                uint4 ah1 = *(const uint4*)(Ahi + (2 * kk2 + 1) * 128 + lane * 4);
#pragma unroll
                for (int nt = 0; nt < 8; nt++) {
                    uint4 bb = *(const uint4*)(B + nt * NT_STRIDE + lane * L_STRIDE + kk2 * 4);
                    MMA_TF32(acc[nt], ah0.x, ah0.y, ah0.z, ah0.w, bb.x, bb.y);
                    MMA_TF32(acc[nt], ah1.x, ah1.y, ah1.z, ah1.w, bb.z, bb.w);
                }
            }
            // Epilogue: d2 = ||c||^2 - 2 S. D frag: c0=(g,2tig) c1=(g,2tig+1)
            // c2=(g+8,2tig) c3=(g+8,2tig+1). Packed u64 min = first-idx ties.
            const int chunk = p >> 1;
#pragma unroll
            for (int nt = 0; nt < 8; nt++) {
                const int cols0 = chunk * 64 + nt * 8 + 2 * tig;
                float2 nrm = __ldg((const float2*)(g_cnorm + cols0));
                float d2;
                unsigned long long key;
                d2 = fmaf(-2.f, acc[nt][0], nrm.x);
                key = ((unsigned long long)ord_f32(d2) << 32) | (unsigned)cols0;
                if (key < best0) best0 = key;
                d2 = fmaf(-2.f, acc[nt][1], nrm.y);
                key = ((unsigned long long)ord_f32(d2) << 32) | (unsigned)(cols0 + 1);
                if (key < best0) best0 = key;
                d2 = fmaf(-2.f, acc[nt][2], nrm.x);
                key = ((unsigned long long)ord_f32(d2) << 32) | (unsigned)cols0;
                if (key < best1) best1 = key;
                d2 = fmaf(-2.f, acc[nt][3], nrm.y);
                key = ((unsigned long long)ord_f32(d2) << 32) | (unsigned)(cols0 + 1);
                if (key < best1) best1 = key;
            }
        }
    }

    // Reduce across the 4 lanes of each group (xor 1, 2 stays in-quad).
#pragma unroll
    for (int off = 1; off <= 2; off <<= 1) {
        unsigned long long o0 = __shfl_xor_sync(0xFFFFFFFFu, best0, off);
        unsigned long long o1 = __shfl_xor_sync(0xFFFFFFFFu, best1, off);
        if (o0 < best0) best0 = o0;
        if (o1 < best1) best1 = o1;
    }

    __syncthreads();   // done with A/B smem
    int* bidx = (int*)smem;   // 128 ints
    if (tig == 0) {
        bidx[w * 16 + g]     = (int)(best0 & 0xFFFFFFFFull);
        bidx[w * 16 + g + 8] = (int)(best1 & 0xFFFFFFFFull);
    }
    __syncthreads();

    // Gather winning rows coalesced, then transposed store.
    float* tmp = smem + 256;   // [128][68]
    for (int i = tid; i < PTS * 16; i += NTHREADS) {
        int pp = i >> 4;
        int d4 = (i & 15) * 4;
        *(float4*)(tmp + pp * 68 + d4) =
            *(const float4*)(cb + (size_t)bidx[pp] * DD + d4);
    }
    __syncthreads();
    float* qbase = out + (size_t)b * (DD * 4096) + (size_t)h0 * 64;
    for (int i = tid; i < DD * 32; i += NTHREADS) {
        int d  = i >> 5;
        int p4 = (i & 31) * 4;
        float4 v;
        v.x = tmp[(p4 + 0) * 68 + d];
        v.y = tmp[(p4 + 1) * 68 + d];
        v.z = tmp[(p4 + 2) * 68 + d];
        v.w = tmp[(p4 + 3) * 68 + d];
        *(float4*)(qbase + (size_t)d * 4096 + (p4 >> 6) * 64 + (p4 & 63)) = v;
    }

    if (write_idx && tid < PTS) {
        out[(size_t)4194304 + (size_t)bh0 * 64 + tid] = (float)bidx[tid];
    }
}

// ---------------- launch -----------------------------------------------------
extern "C" void kernel_launch(void* const* d_in, const int* in_sizes, int n_in,
                              void* d_out, int out_size) {
    const float* x  = (const float*)d_in[0];
    const float* cb = (const float*)d_in[1];
    if (n_in >= 2 && in_sizes[0] == KTOT * DD && in_sizes[1] == 16 * 64 * 64 * 64) {
        x  = (const float*)d_in[1];
        cb = (const float*)d_in[0];
    }
    float* out = (float*)d_out;

    const int smem_bytes = SMEM_FLOATS * (int)sizeof(float);
    cudaFuncSetAttribute(vq_main, cudaFuncAttributeMaxDynamicSharedMemorySize,
                         smem_bytes);

    int write_idx = (out_size >= 4194304 + 65536) ? 1 : 0;
    prep_cb<<<(KTOT + NTHREADS - 1) / NTHREADS, NTHREADS>>>(cb);
    vq_main<<<512, NTHREADS, smem_bytes>>>(x, cb, out, write_idx);
}

// round 14
// speedup vs baseline: 1.4050x; 1.0044x over previous
#include <cuda_runtime.h>
#include <cstdint>

// VQ nearest-codebook via mma.sync m16n8k8 tf32, 3-term Dekker split
// (S = Xhi*Chi + Xlo*Chi + Xhi*Clo), fused argmin.
// CTA = 128 points, 4 warps of 32 points (two m16 tiles) x all 1024 cw.
// 128-thread CTA -> 2 CTAs/SM with up to 256 regs (no 128-reg cliff).

#define DD 64
#define KTOT 1024
#define PTS 128
#define NTHREADS 128
#define NCHUNK 16            // chunks of 64 codewords
#define CHUNK_F 5120         // floats per permuted B chunk
#define NT_STRIDE 640        // 32 lanes * 20
#define L_STRIDE 20          // padded lane stride (conflict-free)

// smem float offsets
#define A_HI_OFF 0           // 8 tiles * 1024
#define A_LO_OFF 8192
#define B0_OFF   16384
#define B1_OFF   21504
#define SMEM_FLOATS 26624    // 104 KB

__device__ float g_Bhi[NCHUNK * CHUNK_F];
__device__ float g_Blo[NCHUNK * CHUNK_F];
__device__ float g_cnorm[KTOT];

#define CP_ASYNC16(dst, src) \
    asm volatile("cp.async.ca.shared.global [%0], [%1], 16;" :: "r"(dst), "l"(src))
#define CP_COMMIT() asm volatile("cp.async.commit_group;" ::: "memory")
#define CP_WAIT0()  asm volatile("cp.async.wait_group 0;" ::: "memory")

#define MMA_TF32(d, a0, a1, a2, a3, b0, b1)                                    \
    asm volatile("mma.sync.aligned.m16n8k8.row.col.f32.tf32.tf32.f32 "         \
        "{%0,%1,%2,%3}, {%4,%5,%6,%7}, {%8,%9}, {%0,%1,%2,%3};"                \
        : "+f"((d)[0]), "+f"((d)[1]), "+f"((d)[2]), "+f"((d)[3])               \
        : "r"(a0), "r"(a1), "r"(a2), "r"(a3), "r"(b0), "r"(b1))

__device__ __forceinline__ float tf32r(float v) {
    uint32_t r;
    asm("cvt.rna.tf32.f32 %0, %1;" : "=r"(r) : "f"(v));
    return __uint_as_float(r);
}
__device__ __forceinline__ uint32_t ord_f32(float f) {
    uint32_t u = __float_as_uint(f);
    return (u & 0x80000000u) ? ~u : (u | 0x80000000u);
}

// ---- prep: tf32 hi/lo codebook permuted into B-fragment order --------------
__global__ void __launch_bounds__(256)
prep_cb(const float* __restrict__ cb) {
    int k = blockIdx.x * blockDim.x + threadIdx.x;
    if (k >= KTOT) return;
    const int chunk = k >> 6, ck = k & 63, nt = ck >> 3, g = ck & 7;
    float s = 0.f;
#pragma unroll
    for (int d = 0; d < DD; d++) {
        float v = cb[(size_t)k * DD + d];
        s += v * v;
        float hi = tf32r(v);
        float lo = tf32r(v - hi);
        int kk = d >> 3, c = d & 7, tig = c & 3, reg = c >> 2;
        int addr = chunk * CHUNK_F + nt * NT_STRIDE + (g * 4 + tig) * L_STRIDE
                 + kk * 2 + reg;
        g_Bhi[addr] = hi;
        g_Blo[addr] = lo;
    }
    g_cnorm[k] = s;
}

// ---- main: GEMM + fused argmin + gather -----------------------------------
__global__ void __launch_bounds__(NTHREADS, 2)
vq_main(const float* __restrict__ x, const float* __restrict__ cb,
        float* __restrict__ out, int write_idx) {
    extern __shared__ float smem[];
    const int tid  = threadIdx.x;
    const int w    = tid >> 5;      // 0..3; warp owns tiles 2w, 2w+1
    const int lane = tid & 31;
    const int g    = lane >> 2;
    const int tig  = lane & 3;

    const int bh0 = blockIdx.x * 2;
    const int b   = bh0 >> 6;
    const int h0  = bh0 & 63;
    const float* xbase = x + (size_t)b * (DD * 4096) + (size_t)h0 * 64;

    uint32_t sbase;
    asm("{ .reg .u64 t; cvta.to.shared.u64 t, %1; cvt.u32.u64 %0, t; }"
        : "=r"(sbase) : "l"(smem));

    // Prefetch phase 0 (chunk 0 hi). 40 floats/thread linear.
#pragma unroll
    for (int q = 0; q < 10; q++)
        CP_ASYNC16(sbase + (uint32_t)(B0_OFF + tid * 40 + q * 4) * 4u,
                   g_Bhi + tid * 40 + q * 4);
    CP_COMMIT();

    // Stage A: x -> tf32 hi/lo in fragment order (8 m16 tiles).
    for (int i = tid; i < DD * 32; i += NTHREADS) {
        int d  = i >> 5;
        int p4 = (i & 31) * 4;
        float4 v = *(const float4*)(xbase + (size_t)d * 4096 + (p4 >> 6) * 64 + (p4 & 63));
        float e[4] = {v.x, v.y, v.z, v.w};
        int kk = d >> 3, c = d & 7, tg = c & 3, chalf = (c >> 2) * 2;
#pragma unroll
        for (int q = 0; q < 4; q++) {
            int p = p4 + q, tt = p >> 4, r = p & 15, gg = r & 7, half = r >> 3;
            int idx = tt * 1024 + kk * 128 + (gg * 4 + tg) * 4 + chalf + half;
            float hi = tf32r(e[q]);
            smem[A_HI_OFF + idx] = hi;
            smem[A_LO_OFF + idx] = tf32r(e[q] - hi);
        }
    }

    const float* AhiA = smem + A_HI_OFF + (2 * w + 0) * 1024;
    const float* AhiB = smem + A_HI_OFF + (2 * w + 1) * 1024;
    const float* AloA = smem + A_LO_OFF + (2 * w + 0) * 1024;
    const float* AloB = smem + A_LO_OFF + (2 * w + 1) * 1024;

    unsigned long long bestA0 = ~0ull, bestA1 = ~0ull;  // tile A rows g, g+8
    unsigned long long bestB0 = ~0ull, bestB1 = ~0ull;  // tile B rows g, g+8
    float accA[8][4], accB[8][4];

    for (int p = 0; p < 32; p++) {
        CP_WAIT0();
        __syncthreads();

        if (p + 1 < 32) {
            const int pc = (p + 1) >> 1;
            const float* src = (((p + 1) & 1) ? g_Blo : g_Bhi) + pc * CHUNK_F;
            const uint32_t dstb =
                sbase + (uint32_t)((((p + 1) & 1) ? B1_OFF : B0_OFF)) * 4u;
#pragma unroll
            for (int q = 0; q < 10; q++)
                CP_ASYNC16(dstb + (uint32_t)(tid * 40 + q * 4) * 4u,
                           src + tid * 40 + q * 4);
            CP_COMMIT();
        }

        const float* B = smem + ((p & 1) ? B1_OFF : B0_OFF);

        if (!(p & 1)) {   // hi chunk: Xhi*Bhi + Xlo*Bhi, acc reset
#pragma unroll
            for (int nt = 0; nt < 8; nt++)
#pragma unroll
                for (int c = 0; c < 4; c++) { accA[nt][c] = 0.f; accB[nt][c] = 0.f; }
#pragma unroll
            for (int kk2 = 0; kk2 < 4; kk2++) {
                uint4 ah0a = *(const uint4*)(AhiA + (2 * kk2 + 0) * 128 + lane * 4);
                uint4 ah1a = *(const uint4*)(AhiA + (2 * kk2 + 1) * 128 + lane * 4);
                uint4 al0a = *(const uint4*)(AloA + (2 * kk2 + 0) * 128 + lane * 4);
                uint4 al1a = *(const uint4*)(AloA + (2 * kk2 + 1) * 128 + lane * 4);
                uint4 ah0b = *(const uint4*)(AhiB + (2 * kk2 + 0) * 128 + lane * 4);
                uint4 ah1b = *(const uint4*)(AhiB + (2 * kk2 + 1) * 128 + lane * 4);
                uint4 al0b = *(const uint4*)(AloB + (2 * kk2 + 0) * 128 + lane * 4);
                uint4 al1b = *(const uint4*)(AloB + (2 * kk2 + 1) * 128 + lane * 4);
#pragma unroll
                for (int nt = 0; nt < 8; nt++) {
                    uint4 bb = *(const uint4*)(B + nt * NT_STRIDE + lane * L_STRIDE + kk2 * 4);
                    MMA_TF32(accA[nt], ah0a.x, ah0a.y, ah0a.z, ah0a.w, bb.x, bb.y);
                    MMA_TF32(accA[nt], ah1a.x, ah1a.y, ah1a.z, ah1a.w, bb.z, bb.w);
                    MMA_TF32(accA[nt], al0a.x, al0a.y, al0a.z, al0a.w, bb.x, bb.y);
                    MMA_TF32(accA[nt], al1a.x, al1a.y, al1a.z, al1a.w, bb.z, bb.w);
                    MMA_TF32(accB[nt], ah0b.x, ah0b.y, ah0b.z, ah0b.w, bb.x, bb.y);
                    MMA_TF32(accB[nt], ah1b.x, ah1b.y, ah1b.z, ah1b.w, bb.z, bb.w);
                    MMA_TF32(accB[nt], al0b.x, al0b.y, al0b.z, al0b.w, bb.x, bb.y);
                    MMA_TF32(accB[nt], al1b.x, al1b.y, al1b.z, al1b.w, bb.z, bb.w);
                }
            }
        } else {          // lo chunk: Xhi*Blo, then epilogue
#pragma unroll
            for (int kk2 = 0; kk2 < 4; kk2++) {
                uint4 ah0a = *(const uint4*)(AhiA + (2 * kk2 + 0) * 128 + lane * 4);
                uint4 ah1a = *(const uint4*)(AhiA + (2 * kk2 + 1) * 128 + lane * 4);
                uint4 ah0b = *(const uint4*)(AhiB + (2 * kk2 + 0) * 128 + lane * 4);
                uint4 ah1b = *(const uint4*)(AhiB + (2 * kk2 + 1) * 128 + lane * 4);
#pragma unroll
                for (int nt = 0; nt < 8; nt++) {
                    uint4 bb = *(const uint4*)(B + nt * NT_STRIDE + lane * L_STRIDE + kk2 * 4);
                    MMA_TF32(accA[nt], ah0a.x, ah0a.y, ah0a.z, ah0a.w, bb.x, bb.y);
                    MMA_TF32(accA[nt], ah1a.x, ah1a.y, ah1a.z, ah1a.w, bb.z, bb.w);
                    MMA_TF32(accB[nt], ah0b.x, ah0b.y, ah0b.z, ah0b.w, bb.x, bb.y);
                    MMA_TF32(accB[nt], ah1b.x, ah1b.y, ah1b.z, ah1b.w, bb.z, bb.w);
                }
            }
            const int chunk = p >> 1;
#pragma unroll
            for (int nt = 0; nt < 8; nt++) {
                const int cols0 = chunk * 64 + nt * 8 + 2 * tig;
                float2 nrm = __ldg((const float2*)(g_cnorm + cols0));
                float d2;
                unsigned long long key;
                d2 = fmaf(-2.f, accA[nt][0], nrm.x);
                key = ((unsigned long long)ord_f32(d2) << 32) | (unsigned)cols0;
                if (key < bestA0) bestA0 = key;
                d2 = fmaf(-2.f, accA[nt][1], nrm.y);
                key = ((unsigned long long)ord_f32(d2) << 32) | (unsigned)(cols0 + 1);
                if (key < bestA0) bestA0 = key;
                d2 = fmaf(-2.f, accA[nt][2], nrm.x);
                key = ((unsigned long long)ord_f32(d2) << 32) | (unsigned)cols0;
                if (key < bestA1) bestA1 = key;
                d2 = fmaf(-2.f, accA[nt][3], nrm.y);
                key = ((unsigned long long)ord_f32(d2) << 32) | (unsigned)(cols0 + 1);
                if (key < bestA1) bestA1 = key;
                d2 = fmaf(-2.f, accB[nt][0], nrm.x);
                key = ((unsigned long long)ord_f32(d2) << 32) | (unsigned)cols0;
                if (key < bestB0) bestB0 = key;
                d2 = fmaf(-2.f, accB[nt][1], nrm.y);
                key = ((unsigned long long)ord_f32(d2) << 32) | (unsigned)(cols0 + 1);
                if (key < bestB0) bestB0 = key;
                d2 = fmaf(-2.f, accB[nt][2], nrm.x);
                key = ((unsigned long long)ord_f32(d2) << 32) | (unsigned)cols0;
                if (key < bestB1) bestB1 = key;
                d2 = fmaf(-2.f, accB[nt][3], nrm.y);
                key = ((unsigned long long)ord_f32(d2) << 32) | (unsigned)(cols0 + 1);
                if (key < bestB1) bestB1 = key;
            }
        }
    }

    // Reduce across the 4 lanes of each group.
#pragma unroll
    for (int off = 1; off <= 2; off <<= 1) {
        unsigned long long t;
        t = __shfl_xor_sync(0xFFFFFFFFu, bestA0, off); if (t < bestA0) bestA0 = t;
        t = __shfl_xor_sync(0xFFFFFFFFu, bestA1, off); if (t < bestA1) bestA1 = t;
        t = __shfl_xor_sync(0xFFFFFFFFu, bestB0, off); if (t < bestB0) bestB0 = t;
        t = __shfl_xor_sync(0xFFFFFFFFu, bestB1, off); if (t < bestB1) bestB1 = t;
    }

    __syncthreads();
    int* bidx = (int*)smem;   // 128 ints
    if (tig == 0) {
        bidx[w * 32 + g]          = (int)(bestA0 & 0xFFFFFFFFull);
        bidx[w * 32 + g + 8]      = (int)(bestA1 & 0xFFFFFFFFull);
        bidx[w * 32 + 16 + g]     = (int)(bestB0 & 0xFFFFFFFFull);
        bidx[w * 32 + 16 + g + 8] = (int)(bestB1 & 0xFFFFFFFFull);
    }
    __syncthreads();

    // Gather winning rows coalesced, then transposed store.
    float* tmp = smem + 256;   // [128][68]
    for (int i = tid; i < PTS * 16; i += NTHREADS) {
        int pp = i >> 4;
        int d4 = (i & 15) * 4;
        *(float4*)(tmp + pp * 68 + d4) =
            *(const float4*)(cb + (size_t)bidx[pp] * DD + d4);
    }
    __syncthreads();
    float* qbase = out + (size_t)b * (DD * 4096) + (size_t)h0 * 64;
    for (int i = tid; i < DD * 32; i += NTHREADS) {
        int d  = i >> 5;
        int p4 = (i & 31) * 4;
        float4 v;
        v.x = tmp[(p4 + 0) * 68 + d];
        v.y = tmp[(p4 + 1) * 68 + d];
        v.z = tmp[(p4 + 2) * 68 + d];
        v.w = tmp[(p4 + 3) * 68 + d];
        *(float4*)(qbase + (size_t)d * 4096 + (p4 >> 6) * 64 + (p4 & 63)) = v;
    }

    if (write_idx && tid < PTS) {
        out[(size_t)4194304 + (size_t)bh0 * 64 + tid] = (float)bidx[tid];
    }
}

// ---------------- launch -----------------------------------------------------
extern "C" void kernel_launch(void* const* d_in, const int* in_sizes, int n_in,
                              void* d_out, int out_size) {
    const float* x  = (const float*)d_in[0];
    const float* cb = (const float*)d_in[1];
    if (n_in >= 2 && in_sizes[0] == KTOT * DD && in_sizes[1] == 16 * 64 * 64 * 64) {
        x  = (const float*)d_in[1];
        cb = (const float*)d_in[0];
    }
    float* out = (float*)d_out;

    const int smem_bytes = SMEM_FLOATS * (int)sizeof(float);
    cudaFuncSetAttribute(vq_main, cudaFuncAttributeMaxDynamicSharedMemorySize,
                         smem_bytes);

    int write_idx = (out_size >= 4194304 + 65536) ? 1 : 0;
    prep_cb<<<(KTOT + 255) / 256, 256>>>(cb);
    vq_main<<<512, NTHREADS, smem_bytes>>>(x, cb, out, write_idx);
}